// round 3
// baseline (speedup 1.0000x reference)
#include <cuda_runtime.h>

// Problem constants
#define NB 4
#define NS 2048
#define ND 1024
#define NH 16
#define NDK 64
#define NM (NB*NS)   // 8192

// Persistent scratch (device globals: allocation-free, graph-safe)
__device__ float g_q[(size_t)NM * ND];    // [B,H,S,dk]
__device__ float g_k[(size_t)NM * ND];    // [B,H,S,dk]
__device__ float g_v[(size_t)NM * ND];    // [B,H,S,dk]
__device__ float g_ctx[(size_t)NM * ND];  // [B,S,D]

// ---------------------------------------------------------------------------
// GEMM: out[m,n] = sum_k X[m,k] * W[n,k] + bias[n]
// X: [M,1024] row-major, W: [1024,1024] row-major (used transposed).
// out_sel 0/1/2 -> g_q/g_k/g_v written in [B,H,S,dk] layout
// out_sel 3     -> plain [M,1024] (final output)
// x_sel 0 -> Xin param, 1 -> g_ctx
// 128x128 block, BK=16, 256 threads, 8x8 microtile, double-buffered smem.
// ---------------------------------------------------------------------------
__global__ __launch_bounds__(256, 2)
void gemm_bias_k(const float* __restrict__ Xin, int x_sel,
                 const float* __restrict__ W, const float* __restrict__ bias,
                 float* __restrict__ Oout, int out_sel)
{
    const float* X = (x_sel == 0) ? Xin : g_ctx;
    float* out;
    if      (out_sel == 0) out = g_q;
    else if (out_sel == 1) out = g_k;
    else if (out_sel == 2) out = g_v;
    else                   out = Oout;

    __shared__ float As[2][16][132];   // [stage][k][m], padded
    __shared__ float Bs[2][16][132];   // [stage][k][n], padded

    const int tid  = threadIdx.x;
    const int tx   = tid & 15;
    const int ty   = tid >> 4;
    const int row0 = blockIdx.y * 128;
    const int col0 = blockIdx.x * 128;

    float acc[8][8];
    #pragma unroll
    for (int i = 0; i < 8; i++)
        #pragma unroll
        for (int j = 0; j < 8; j++) acc[i][j] = 0.f;

    // Prologue: load k-slice 0 into stage 0
    #pragma unroll
    for (int w = 0; w < 2; w++) {
        int f  = tid + w * 256;       // 0..511
        int r  = f >> 2;              // 0..127
        int kb = (f & 3) << 2;        // 0,4,8,12
        float4 a = *(const float4*)(X + (size_t)(row0 + r) * ND + kb);
        As[0][kb+0][r] = a.x; As[0][kb+1][r] = a.y;
        As[0][kb+2][r] = a.z; As[0][kb+3][r] = a.w;
        float4 b = *(const float4*)(W + (size_t)(col0 + r) * ND + kb);
        Bs[0][kb+0][r] = b.x; Bs[0][kb+1][r] = b.y;
        Bs[0][kb+2][r] = b.z; Bs[0][kb+3][r] = b.w;
    }
    __syncthreads();

    for (int k0 = 0; k0 < ND; k0 += 16) {
        const int buf = (k0 >> 4) & 1;
        const int nxt = buf ^ 1;
        const bool more = (k0 + 16) < ND;

        // Issue next-stage global loads early (latency hidden under FMAs)
        float4 pa[2], pb[2];
        if (more) {
            #pragma unroll
            for (int w = 0; w < 2; w++) {
                int f  = tid + w * 256;
                int r  = f >> 2;
                int kb = (f & 3) << 2;
                pa[w] = *(const float4*)(X + (size_t)(row0 + r) * ND + k0 + 16 + kb);
                pb[w] = *(const float4*)(W + (size_t)(col0 + r) * ND + k0 + 16 + kb);
            }
        }

        // Compute on current stage
        #pragma unroll
        for (int kk = 0; kk < 16; kk++) {
            float4 a0 = *(const float4*)&As[buf][kk][ty*8];
            float4 a1 = *(const float4*)&As[buf][kk][ty*8+4];
            float4 b0 = *(const float4*)&Bs[buf][kk][tx*8];
            float4 b1 = *(const float4*)&Bs[buf][kk][tx*8+4];
            float av[8] = {a0.x,a0.y,a0.z,a0.w,a1.x,a1.y,a1.z,a1.w};
            float bv[8] = {b0.x,b0.y,b0.z,b0.w,b1.x,b1.y,b1.z,b1.w};
            #pragma unroll
            for (int i = 0; i < 8; i++)
                #pragma unroll
                for (int j = 0; j < 8; j++)
                    acc[i][j] = fmaf(av[i], bv[j], acc[i][j]);
        }

        // Commit next stage and sync
        if (more) {
            #pragma unroll
            for (int w = 0; w < 2; w++) {
                int f  = tid + w * 256;
                int r  = f >> 2;
                int kb = (f & 3) << 2;
                As[nxt][kb+0][r] = pa[w].x; As[nxt][kb+1][r] = pa[w].y;
                As[nxt][kb+2][r] = pa[w].z; As[nxt][kb+3][r] = pa[w].w;
                Bs[nxt][kb+0][r] = pb[w].x; Bs[nxt][kb+1][r] = pb[w].y;
                Bs[nxt][kb+2][r] = pb[w].z; Bs[nxt][kb+3][r] = pb[w].w;
            }
            __syncthreads();
        }
    }

    float bb[8];
    #pragma unroll
    for (int j = 0; j < 8; j++) bb[j] = bias[col0 + tx*8 + j];

    #pragma unroll
    for (int i = 0; i < 8; i++) {
        int m = row0 + ty*8 + i;
        float o[8];
        #pragma unroll
        for (int j = 0; j < 8; j++) o[j] = acc[i][j] + bb[j];
        float* dst;
        if (out_sel <= 2) {
            int bt = m >> 11;            // batch
            int s  = m & (NS - 1);       // sequence pos
            int n  = col0 + tx*8;
            int h  = n >> 6;             // head (constant across j: 8 | 64)
            int d0 = n & 63;
            dst = out + (((size_t)(bt*NH + h) * NS + s) * NDK + d0);
        } else {
            dst = out + (size_t)m * ND + col0 + tx*8;
        }
        *(float4*)(dst)     = make_float4(o[0], o[1], o[2], o[3]);
        *(float4*)(dst + 4) = make_float4(o[4], o[5], o[6], o[7]);
    }
}

// ---------------------------------------------------------------------------
// Flash attention: per block = (batch b, head h, 128-row q tile).
// Streams K/V in 64-row tiles, online softmax with relpos bias, writes g_ctx.
// blockIdx.x = b + 4*qt  (batch fastest -> 4 batches share relpos lines in L2)
// ---------------------------------------------------------------------------
#define QT 128
#define KT 64
#define ATTN_SMEM ((QT*65 + KT*65 + KT*64 + QT*64) * 4)   // 99072 bytes

__global__ __launch_bounds__(256)
void attn_k(const float* __restrict__ relpos)
{
    extern __shared__ float sm[];
    float (*qs)[65] = (float(*)[65])(sm);                        // [128][65]
    float (*ks)[65] = (float(*)[65])(sm + QT*65);                // [64][65]
    float (*vs)[64] = (float(*)[64])(sm + QT*65 + KT*65);        // [64][64]
    float (*ps)[64] = (float(*)[64])(sm + QT*65 + KT*65 + KT*64);// [128][64]

    const int b   = blockIdx.x & (NB - 1);
    const int qt  = blockIdx.x >> 2;
    const int h   = blockIdx.y;
    const int tid = threadIdx.x;
    const int tx  = tid & 15;     // 16 cols of threads
    const int ty  = tid >> 4;     // 16 rows of threads

    const float* qptr  = g_q + ((size_t)(b*NH + h) * NS + (size_t)qt*QT) * NDK;
    const float* kbase = g_k + ((size_t)(b*NH + h) * NS) * NDK;
    const float* vbase = g_v + ((size_t)(b*NH + h) * NS) * NDK;
    const float* bias_base = relpos + ((size_t)h * NS + (size_t)qt*QT) * NS;

    // Load 128x64 q tile
    #pragma unroll
    for (int w = 0; w < 8; w++) {
        int f = tid + w*256;          // 0..2047
        int r = f >> 4;               // 0..127
        int d = (f & 15) << 2;        // 0..60
        float4 a = *(const float4*)(qptr + (size_t)r * NDK + d);
        qs[r][d] = a.x; qs[r][d+1] = a.y; qs[r][d+2] = a.z; qs[r][d+3] = a.w;
    }

    float m_i[8], l_i[8], ctx[8][4];
    #pragma unroll
    for (int i = 0; i < 8; i++) {
        m_i[i] = -1e30f; l_i[i] = 0.f;
        #pragma unroll
        for (int j = 0; j < 4; j++) ctx[i][j] = 0.f;
    }

    for (int kt = 0; kt < NS/KT; kt++) {
        __syncthreads();   // protect ks/vs (prev gemm2) and qs (first iter)
        // Load 64x64 K and V tiles
        #pragma unroll
        for (int w = 0; w < 4; w++) {
            int f = tid + w*256;
            int r = f >> 4;
            int d = (f & 15) << 2;
            float4 a = *(const float4*)(kbase + (size_t)(kt*KT + r) * NDK + d);
            ks[r][d] = a.x; ks[r][d+1] = a.y; ks[r][d+2] = a.z; ks[r][d+3] = a.w;
            float4 v = *(const float4*)(vbase + (size_t)(kt*KT + r) * NDK + d);
            *(float4*)&vs[r][d] = v;
        }
        __syncthreads();

        // GEMM1: s[8][4] = q-rows(ty*8..) . k-rows(tx*4..)
        float s[8][4];
        #pragma unroll
        for (int i = 0; i < 8; i++)
            #pragma unroll
            for (int j = 0; j < 4; j++) s[i][j] = 0.f;

        #pragma unroll 8
        for (int d = 0; d < NDK; d++) {
            float qa[8], kb[4];
            #pragma unroll
            for (int i = 0; i < 8; i++) qa[i] = qs[ty*8 + i][d];
            #pragma unroll
            for (int j = 0; j < 4; j++) kb[j] = ks[tx*4 + j][d];
            #pragma unroll
            for (int i = 0; i < 8; i++)
                #pragma unroll
                for (int j = 0; j < 4; j++)
                    s[i][j] = fmaf(qa[i], kb[j], s[i][j]);
        }

        // scale + relpos bias + online softmax (row groups of 16 lanes)
        #pragma unroll
        for (int i = 0; i < 8; i++) {
            float4 bv4 = *(const float4*)(bias_base + (size_t)(ty*8 + i) * NS
                                          + kt*KT + tx*4);
            s[i][0] = fmaf(s[i][0], 0.125f, bv4.x);
            s[i][1] = fmaf(s[i][1], 0.125f, bv4.y);
            s[i][2] = fmaf(s[i][2], 0.125f, bv4.z);
            s[i][3] = fmaf(s[i][3], 0.125f, bv4.w);

            float tm = fmaxf(fmaxf(s[i][0], s[i][1]), fmaxf(s[i][2], s[i][3]));
            tm = fmaxf(tm, __shfl_xor_sync(0xffffffffu, tm, 1));
            tm = fmaxf(tm, __shfl_xor_sync(0xffffffffu, tm, 2));
            tm = fmaxf(tm, __shfl_xor_sync(0xffffffffu, tm, 4));
            tm = fmaxf(tm, __shfl_xor_sync(0xffffffffu, tm, 8));

            float nm   = fmaxf(m_i[i], tm);
            float corr = __expf(m_i[i] - nm);
            float rs = 0.f;
            #pragma unroll
            for (int j = 0; j < 4; j++) { s[i][j] = __expf(s[i][j] - nm); rs += s[i][j]; }
            rs += __shfl_xor_sync(0xffffffffu, rs, 1);
            rs += __shfl_xor_sync(0xffffffffu, rs, 2);
            rs += __shfl_xor_sync(0xffffffffu, rs, 4);
            rs += __shfl_xor_sync(0xffffffffu, rs, 8);

            l_i[i] = l_i[i] * corr + rs;
            m_i[i] = nm;
            #pragma unroll
            for (int j = 0; j < 4; j++) ctx[i][j] *= corr;

            *(float4*)&ps[ty*8 + i][tx*4] = make_float4(s[i][0], s[i][1], s[i][2], s[i][3]);
        }
        __syncthreads();

        // GEMM2: ctx += P @ V
        #pragma unroll 8
        for (int c = 0; c < KT; c++) {
            float4 vb = *(const float4*)&vs[c][tx*4];
            #pragma unroll
            for (int i = 0; i < 8; i++) {
                float pa = ps[ty*8 + i][c];
                ctx[i][0] = fmaf(pa, vb.x, ctx[i][0]);
                ctx[i][1] = fmaf(pa, vb.y, ctx[i][1]);
                ctx[i][2] = fmaf(pa, vb.z, ctx[i][2]);
                ctx[i][3] = fmaf(pa, vb.w, ctx[i][3]);
            }
        }
    }

    // Normalize and write to g_ctx [B,S,D] (heads recombined)
    #pragma unroll
    for (int i = 0; i < 8; i++) {
        float inv = 1.f / l_i[i];
        float* dst = g_ctx + ((size_t)(b*NS + qt*QT + ty*8 + i) * ND) + h*NDK + tx*4;
        *(float4*)dst = make_float4(ctx[i][0]*inv, ctx[i][1]*inv,
                                    ctx[i][2]*inv, ctx[i][3]*inv);
    }
}

// ---------------------------------------------------------------------------
extern "C" void kernel_launch(void* const* d_in, const int* in_sizes, int n_in,
                              void* d_out, int out_size)
{
    const float* Q      = (const float*)d_in[0];
    const float* K      = (const float*)d_in[1];
    const float* V      = (const float*)d_in[2];
    const float* Wq     = (const float*)d_in[3];
    const float* bq     = (const float*)d_in[4];
    const float* Wk     = (const float*)d_in[5];
    const float* bk     = (const float*)d_in[6];
    const float* Wv     = (const float*)d_in[7];
    const float* bv     = (const float*)d_in[8];
    const float* Wo     = (const float*)d_in[9];
    const float* bo     = (const float*)d_in[10];
    const float* relpos = (const float*)d_in[11];
    float* out = (float*)d_out;

    cudaFuncSetAttribute(attn_k, cudaFuncAttributeMaxDynamicSharedMemorySize,
                         ATTN_SMEM);

    dim3 gproj(ND/128, NM/128);   // (8, 64)

    gemm_bias_k<<<gproj, 256>>>(Q, 0, Wq, bq, nullptr, 0);
    gemm_bias_k<<<gproj, 256>>>(K, 0, Wk, bk, nullptr, 1);
    gemm_bias_k<<<gproj, 256>>>(V, 0, Wv, bv, nullptr, 2);

    dim3 gattn(NB * (NS/QT), NH); // (64, 16), batch fastest for L2 bias reuse
    attn_k<<<gattn, 256, ATTN_SMEM>>>(relpos);

    gemm_bias_k<<<gproj, 256>>>(nullptr, 1, Wo, bo, out, 3);
}

// round 4
// speedup vs baseline: 2.6033x; 2.6033x over previous
#include <cuda_runtime.h>
#include <cstdint>

// Problem constants
#define NB 4
#define NS 2048
#define ND 1024
#define NH 16
#define NDK 64
#define NM (NB*NS)   // 8192

// Persistent scratch (device globals: allocation-free, graph-safe)
__device__ float g_q[(size_t)NM * ND];    // [B,H,S,dk] (tf32-rounded)
__device__ float g_k[(size_t)NM * ND];    // [B,H,S,dk] (tf32-rounded)
__device__ float g_v[(size_t)NM * ND];    // [B,H,S,dk] (tf32-rounded)
__device__ float g_ctx[(size_t)NM * ND];  // [B,S,D]    (fp32)

// ---------------------------------------------------------------------------
// tf32 helpers
// ---------------------------------------------------------------------------
__device__ __forceinline__ float f2tf(float x) {
    uint32_t u;
    asm("cvt.rna.tf32.f32 %0, %1;" : "=r"(u) : "f"(x));
    return __uint_as_float(u);
}

__device__ __forceinline__ void mma_tf32(float d[4],
                                         uint32_t a0, uint32_t a1,
                                         uint32_t a2, uint32_t a3,
                                         uint32_t b0, uint32_t b1) {
    asm volatile(
        "mma.sync.aligned.m16n8k8.row.col.f32.tf32.tf32.f32 "
        "{%0,%1,%2,%3}, {%4,%5,%6,%7}, {%8,%9}, {%0,%1,%2,%3};"
        : "+f"(d[0]), "+f"(d[1]), "+f"(d[2]), "+f"(d[3])
        : "r"(a0), "r"(a1), "r"(a2), "r"(a3), "r"(b0), "r"(b1));
}

// ---------------------------------------------------------------------------
// GEMM: out[m,n] = sum_k X[m,k]*W[n,k] + bias[n]   (tf32 tensor cores)
// 128x128 tile, BK=16, 256 threads (8 warps: 4 m x 2 n), warp tile 32x64.
// out_sel 0/1/2 -> g_q/g_k/g_v ([B,H,S,dk], tf32-rounded); 3 -> plain [M,N].
// ---------------------------------------------------------------------------
#define BKG 16

__global__ __launch_bounds__(256, 2)
void gemm_bias_k(const float* __restrict__ Xin, int x_sel,
                 const float* __restrict__ W, const float* __restrict__ bias,
                 float* __restrict__ Oout, int out_sel)
{
    const float* X = (x_sel == 0) ? Xin : g_ctx;
    float* out = (out_sel == 0) ? g_q : (out_sel == 1) ? g_k :
                 (out_sel == 2) ? g_v : Oout;

    __shared__ float As[2][128][20];   // [stage][m][k], pad 20 -> conflict-free frags
    __shared__ float Bs[2][128][20];   // [stage][n][k]

    const int tid  = threadIdx.x;
    const int lane = tid & 31;
    const int warp = tid >> 5;
    const int g    = lane >> 2;   // groupID (rows)
    const int tg   = lane & 3;    // thread-in-group (cols)
    const int wm   = warp & 3;    // 4 warps over m
    const int wn   = warp >> 2;   // 2 warps over n
    const int row0 = blockIdx.y * 128;
    const int col0 = blockIdx.x * 128;

    float d[2][8][4];
    #pragma unroll
    for (int mi = 0; mi < 2; mi++)
        #pragma unroll
        for (int ni = 0; ni < 8; ni++)
            #pragma unroll
            for (int q = 0; q < 4; q++) d[mi][ni][q] = 0.f;

    // Prologue: k-slice 0 into stage 0 (rounded to tf32)
    #pragma unroll
    for (int w = 0; w < 2; w++) {
        int f  = tid + w * 256;
        int r  = f >> 2;
        int kb = (f & 3) << 2;
        float4 a = *(const float4*)(X + (size_t)(row0 + r) * ND + kb);
        float4 b = *(const float4*)(W + (size_t)(col0 + r) * ND + kb);
        *(float4*)&As[0][r][kb] = make_float4(f2tf(a.x), f2tf(a.y), f2tf(a.z), f2tf(a.w));
        *(float4*)&Bs[0][r][kb] = make_float4(f2tf(b.x), f2tf(b.y), f2tf(b.z), f2tf(b.w));
    }
    __syncthreads();

    #pragma unroll 2
    for (int k0 = 0; k0 < ND; k0 += BKG) {
        const int buf = (k0 >> 4) & 1;
        const int nxt = buf ^ 1;
        const bool more = (k0 + BKG) < ND;

        float4 pa[2], pb[2];
        if (more) {
            #pragma unroll
            for (int w = 0; w < 2; w++) {
                int f  = tid + w * 256;
                int r  = f >> 2;
                int kb = (f & 3) << 2;
                pa[w] = *(const float4*)(X + (size_t)(row0 + r) * ND + k0 + BKG + kb);
                pb[w] = *(const float4*)(W + (size_t)(col0 + r) * ND + k0 + BKG + kb);
            }
        }

        // Compute current stage: 2 k8-substeps x 16 MMAs
        #pragma unroll
        for (int k8 = 0; k8 < BKG; k8 += 8) {
            uint32_t af[2][4], bf[8][2];
            #pragma unroll
            for (int mi = 0; mi < 2; mi++) {
                int rm = wm * 32 + mi * 16;
                af[mi][0] = __float_as_uint(As[buf][rm + g    ][k8 + tg]);
                af[mi][1] = __float_as_uint(As[buf][rm + g + 8][k8 + tg]);
                af[mi][2] = __float_as_uint(As[buf][rm + g    ][k8 + tg + 4]);
                af[mi][3] = __float_as_uint(As[buf][rm + g + 8][k8 + tg + 4]);
            }
            #pragma unroll
            for (int ni = 0; ni < 8; ni++) {
                int cn = wn * 64 + ni * 8;
                bf[ni][0] = __float_as_uint(Bs[buf][cn + g][k8 + tg]);
                bf[ni][1] = __float_as_uint(Bs[buf][cn + g][k8 + tg + 4]);
            }
            #pragma unroll
            for (int mi = 0; mi < 2; mi++)
                #pragma unroll
                for (int ni = 0; ni < 8; ni++)
                    mma_tf32(d[mi][ni], af[mi][0], af[mi][1], af[mi][2], af[mi][3],
                             bf[ni][0], bf[ni][1]);
        }

        if (more) {
            #pragma unroll
            for (int w = 0; w < 2; w++) {
                int f  = tid + w * 256;
                int r  = f >> 2;
                int kb = (f & 3) << 2;
                *(float4*)&As[nxt][r][kb] =
                    make_float4(f2tf(pa[w].x), f2tf(pa[w].y), f2tf(pa[w].z), f2tf(pa[w].w));
                *(float4*)&Bs[nxt][r][kb] =
                    make_float4(f2tf(pb[w].x), f2tf(pb[w].y), f2tf(pb[w].z), f2tf(pb[w].w));
            }
            __syncthreads();
        }
    }

    // Epilogue: bias + layout transform
    #pragma unroll
    for (int mi = 0; mi < 2; mi++) {
        #pragma unroll
        for (int ni = 0; ni < 8; ni++) {
            int c0 = col0 + wn * 64 + ni * 8 + tg * 2;
            float2 bb = *(const float2*)(bias + c0);
            int r0 = row0 + wm * 32 + mi * 16 + g;
            float2 v0 = make_float2(d[mi][ni][0] + bb.x, d[mi][ni][1] + bb.y);
            float2 v1 = make_float2(d[mi][ni][2] + bb.x, d[mi][ni][3] + bb.y);
            if (out_sel <= 2) {
                // pre-round so attention consumes tf32-clean data
                v0.x = f2tf(v0.x); v0.y = f2tf(v0.y);
                v1.x = f2tf(v1.x); v1.y = f2tf(v1.y);
                int hh = c0 >> 6, d0 = c0 & 63;
                int bt = r0 >> 11, s0 = r0 & (NS - 1);
                *(float2*)(out + (((size_t)(bt * NH + hh) * NS + s0) * NDK + d0)) = v0;
                int r1 = r0 + 8;
                int bt1 = r1 >> 11, s1 = r1 & (NS - 1);
                *(float2*)(out + (((size_t)(bt1 * NH + hh) * NS + s1) * NDK + d0)) = v1;
            } else {
                *(float2*)(out + (size_t)r0 * ND + c0) = v0;
                *(float2*)(out + (size_t)(r0 + 8) * ND + c0) = v1;
            }
        }
    }
}

// ---------------------------------------------------------------------------
// Flash attention (tf32 tensor cores).
// Block = (b, h, 128-row q tile); 8 warps, each owns 16 q rows.
// Q frags register-resident; KV streamed in 64-row tiles; P via smem
// round-trip (intra-warp); O accumulated in registers.
// ---------------------------------------------------------------------------
#define KSOFF (128*68)
#define VSOFF (128*68 + 64*68)
#define ATTN_SMEM ((128*68 + 64*68 + 64*72) * 4)   // 70656 bytes

__global__ __launch_bounds__(256)
void attn_k(const float* __restrict__ relpos)
{
    extern __shared__ float sm[];
    float (*ps)[68] = (float(*)[68])sm;            // [128][68] P tile
    float (*ks)[68] = (float(*)[68])(sm + KSOFF);  // [64][68]  K tile
    float (*vs)[72] = (float(*)[72])(sm + VSOFF);  // [64][72]  V tile

    const int b    = blockIdx.x & (NB - 1);
    const int qt   = blockIdx.x >> 2;
    const int h    = blockIdx.y;
    const int tid  = threadIdx.x;
    const int lane = tid & 31;
    const int warp = tid >> 5;
    const int g    = lane >> 2;
    const int tg   = lane & 3;

    const float* qptr  = g_q + ((size_t)(b*NH + h) * NS + (size_t)qt*128) * NDK;
    const float* kbase = g_k + ((size_t)(b*NH + h) * NS) * NDK;
    const float* vbase = g_v + ((size_t)(b*NH + h) * NS) * NDK;
    const float* bias0 = relpos + ((size_t)h * NS + (size_t)qt*128 + warp*16) * NS;

    // Q fragments: rows warp*16+g and +8, all 64 k-cols (8 k8 steps)
    uint32_t qa[8][4];
    {
        const float* q0 = qptr + (size_t)(warp*16 + g) * NDK;
        const float* q1 = q0 + 8 * NDK;
        #pragma unroll
        for (int k8 = 0; k8 < 8; k8++) {
            qa[k8][0] = __float_as_uint(q0[k8*8 + tg]);
            qa[k8][1] = __float_as_uint(q1[k8*8 + tg]);
            qa[k8][2] = __float_as_uint(q0[k8*8 + tg + 4]);
            qa[k8][3] = __float_as_uint(q1[k8*8 + tg + 4]);
        }
    }

    float o[8][4];
    #pragma unroll
    for (int ni = 0; ni < 8; ni++)
        #pragma unroll
        for (int q = 0; q < 4; q++) o[ni][q] = 0.f;
    float m0 = -1e30f, m1 = -1e30f, l0 = 0.f, l1 = 0.f;

    for (int kt = 0; kt < NS/64; kt++) {
        __syncthreads();   // ks/vs free (prev iter fully consumed)
        #pragma unroll
        for (int w = 0; w < 4; w++) {
            int f  = tid + w*256;
            int r  = f >> 4;
            int dd = (f & 15) << 2;
            *(float4*)&ks[r][dd] = *(const float4*)(kbase + (size_t)(kt*64 + r)*NDK + dd);
            *(float4*)&vs[r][dd] = *(const float4*)(vbase + (size_t)(kt*64 + r)*NDK + dd);
        }
        __syncthreads();

        // Bias prefetch (overlaps with GEMM1)
        float2 br0[8], br1[8];
        {
            const float* bp0 = bias0 + (size_t)g * NS + kt*64 + tg*2;
            const float* bp1 = bp0 + 8 * NS;
            #pragma unroll
            for (int ni = 0; ni < 8; ni++) {
                br0[ni] = *(const float2*)(bp0 + ni*8);
                br1[ni] = *(const float2*)(bp1 + ni*8);
            }
        }

        // GEMM1: S(16x64 per warp) = Q . K^T
        float s[8][4];
        #pragma unroll
        for (int ni = 0; ni < 8; ni++)
            #pragma unroll
            for (int q = 0; q < 4; q++) s[ni][q] = 0.f;

        #pragma unroll
        for (int k8 = 0; k8 < 8; k8++) {
            uint32_t bf[8][2];
            #pragma unroll
            for (int ni = 0; ni < 8; ni++) {
                bf[ni][0] = __float_as_uint(ks[ni*8 + g][k8*8 + tg]);
                bf[ni][1] = __float_as_uint(ks[ni*8 + g][k8*8 + tg + 4]);
            }
            #pragma unroll
            for (int ni = 0; ni < 8; ni++)
                mma_tf32(s[ni], qa[k8][0], qa[k8][1], qa[k8][2], qa[k8][3],
                         bf[ni][0], bf[ni][1]);
        }

        // Scale + bias + online softmax (thread owns rows g and g+8, 16 cols)
        float nm0 = m0, nm1 = m1;
        #pragma unroll
        for (int ni = 0; ni < 8; ni++) {
            s[ni][0] = fmaf(s[ni][0], 0.125f, br0[ni].x);
            s[ni][1] = fmaf(s[ni][1], 0.125f, br0[ni].y);
            s[ni][2] = fmaf(s[ni][2], 0.125f, br1[ni].x);
            s[ni][3] = fmaf(s[ni][3], 0.125f, br1[ni].y);
            nm0 = fmaxf(nm0, fmaxf(s[ni][0], s[ni][1]));
            nm1 = fmaxf(nm1, fmaxf(s[ni][2], s[ni][3]));
        }
        nm0 = fmaxf(nm0, __shfl_xor_sync(0xffffffffu, nm0, 1));
        nm0 = fmaxf(nm0, __shfl_xor_sync(0xffffffffu, nm0, 2));
        nm1 = fmaxf(nm1, __shfl_xor_sync(0xffffffffu, nm1, 1));
        nm1 = fmaxf(nm1, __shfl_xor_sync(0xffffffffu, nm1, 2));

        float corr0 = __expf(m0 - nm0);
        float corr1 = __expf(m1 - nm1);
        float rs0 = 0.f, rs1 = 0.f;
        const int pr = warp * 16 + g;
        #pragma unroll
        for (int ni = 0; ni < 8; ni++) {
            s[ni][0] = __expf(s[ni][0] - nm0);
            s[ni][1] = __expf(s[ni][1] - nm0);
            s[ni][2] = __expf(s[ni][2] - nm1);
            s[ni][3] = __expf(s[ni][3] - nm1);
            rs0 += s[ni][0] + s[ni][1];
            rs1 += s[ni][2] + s[ni][3];
            int c = ni*8 + tg*2;
            *(float2*)&ps[pr    ][c] = make_float2(f2tf(s[ni][0]), f2tf(s[ni][1]));
            *(float2*)&ps[pr + 8][c] = make_float2(f2tf(s[ni][2]), f2tf(s[ni][3]));
        }
        rs0 += __shfl_xor_sync(0xffffffffu, rs0, 1);
        rs0 += __shfl_xor_sync(0xffffffffu, rs0, 2);
        rs1 += __shfl_xor_sync(0xffffffffu, rs1, 1);
        rs1 += __shfl_xor_sync(0xffffffffu, rs1, 2);
        l0 = l0 * corr0 + rs0;
        l1 = l1 * corr1 + rs1;
        m0 = nm0; m1 = nm1;
        #pragma unroll
        for (int ni = 0; ni < 8; ni++) {
            o[ni][0] *= corr0; o[ni][1] *= corr0;
            o[ni][2] *= corr1; o[ni][3] *= corr1;
        }
        __syncwarp();   // order ps stores before intra-warp frag reloads

        // GEMM2: O += P . V   (A rows are this warp's own P rows)
        #pragma unroll
        for (int k8 = 0; k8 < 8; k8++) {
            uint32_t af[4];
            af[0] = __float_as_uint(ps[warp*16 + g    ][k8*8 + tg]);
            af[1] = __float_as_uint(ps[warp*16 + g + 8][k8*8 + tg]);
            af[2] = __float_as_uint(ps[warp*16 + g    ][k8*8 + tg + 4]);
            af[3] = __float_as_uint(ps[warp*16 + g + 8][k8*8 + tg + 4]);
            uint32_t bf[8][2];
            #pragma unroll
            for (int ni = 0; ni < 8; ni++) {
                bf[ni][0] = __float_as_uint(vs[k8*8 + tg    ][ni*8 + g]);
                bf[ni][1] = __float_as_uint(vs[k8*8 + tg + 4][ni*8 + g]);
            }
            #pragma unroll
            for (int ni = 0; ni < 8; ni++)
                mma_tf32(o[ni], af[0], af[1], af[2], af[3], bf[ni][0], bf[ni][1]);
        }
        // block-wide __syncthreads at top of next iteration protects ps/ks/vs
    }

    // Normalize and write O to g_ctx [B,S,D]
    float inv0 = 1.f / l0, inv1 = 1.f / l1;
    int r0 = qt*128 + warp*16 + g;
    #pragma unroll
    for (int ni = 0; ni < 8; ni++) {
        int c = h*64 + ni*8 + tg*2;
        *(float2*)(g_ctx + (size_t)(b*NS + r0    ) * ND + c) =
            make_float2(o[ni][0]*inv0, o[ni][1]*inv0);
        *(float2*)(g_ctx + (size_t)(b*NS + r0 + 8) * ND + c) =
            make_float2(o[ni][2]*inv1, o[ni][3]*inv1);
    }
}

// ---------------------------------------------------------------------------
extern "C" void kernel_launch(void* const* d_in, const int* in_sizes, int n_in,
                              void* d_out, int out_size)
{
    const float* Q      = (const float*)d_in[0];
    const float* K      = (const float*)d_in[1];
    const float* V      = (const float*)d_in[2];
    const float* Wq     = (const float*)d_in[3];
    const float* bq     = (const float*)d_in[4];
    const float* Wk     = (const float*)d_in[5];
    const float* bk     = (const float*)d_in[6];
    const float* Wv     = (const float*)d_in[7];
    const float* bv     = (const float*)d_in[8];
    const float* Wo     = (const float*)d_in[9];
    const float* bo     = (const float*)d_in[10];
    const float* relpos = (const float*)d_in[11];
    float* out = (float*)d_out;

    cudaFuncSetAttribute(attn_k, cudaFuncAttributeMaxDynamicSharedMemorySize,
                         ATTN_SMEM);

    dim3 gproj(ND/128, NM/128);   // (8, 64)

    gemm_bias_k<<<gproj, 256>>>(Q, 0, Wq, bq, nullptr, 0);
    gemm_bias_k<<<gproj, 256>>>(K, 0, Wk, bk, nullptr, 1);
    gemm_bias_k<<<gproj, 256>>>(V, 0, Wv, bv, nullptr, 2);

    dim3 gattn(NB * (NS/128), NH);  // (64, 16), batch fastest for L2 bias reuse
    attn_k<<<gattn, 256, ATTN_SMEM>>>(relpos);

    gemm_bias_k<<<gproj, 256>>>(nullptr, 1, Wo, bo, out, 3);
}